// round 9
// baseline (speedup 1.0000x reference)
#include <cuda_runtime.h>

// S4/DPLR kernel materialization, H=256, N2=64, RANK=1, CH=1, L=2048.
// Two-phase chunked decomposition:
//  K1: per head, one warp runs the STATE-ONLY T=16 blocked recurrence for
//      (NC-1)*K steps, writing checkpoint states every K steps.
//  K2: H*NC independent warps each expand one K-step chunk (full T=8 blocked
//      recurrence with outputs) from its checkpoint -> throughput-bound.
// Micro-opts both: u64 scatter (no fold FADDs), duplicated-mu smem layout
// (update multipliers via LDS.128, no packing movs), negation-free update.

#define ROWP2 68   // floats per 64-wide padded row (272B, 16B aligned)
#define NCC 8      // chunks

typedef unsigned long long u64;

__device__ float g_ckpt[256 * NCC * 128];   // [h][c][lane*4]: xr0,xr1,xi0,xi1

__device__ __forceinline__ float wsum(float v) {
    #pragma unroll
    for (int o = 16; o; o >>= 1) v += __shfl_xor_sync(0xffffffffu, v, o);
    return v;
}
__device__ __forceinline__ u64 pk(float x, float y) {
    u64 r; asm("mov.b64 %0,{%1,%2};" : "=l"(r) : "f"(x), "f"(y)); return r;
}
__device__ __forceinline__ float2 up(u64 a) {
    float2 v; asm("mov.b64 {%0,%1},%2;" : "=f"(v.x), "=f"(v.y) : "l"(a)); return v;
}
__device__ __forceinline__ u64 f2fma(u64 a, u64 b, u64 c) {
    u64 d; asm("fma.rn.f32x2 %0,%1,%2,%3;" : "=l"(d) : "l"(a), "l"(b), "l"(c)); return d;
}
__device__ __forceinline__ u64 f2mul(u64 a, u64 b) {
    u64 d; asm("mul.rn.f32x2 %0,%1,%2;" : "=l"(d) : "l"(a), "l"(b)); return d;
}
__device__ __forceinline__ u64 f2add(u64 a, u64 b) {
    u64 d; asm("add.rn.f32x2 %0,%1,%2;" : "=l"(d) : "l"(a), "l"(b)); return d;
}

// ---------------- shared per-head setup (computes e,q,u,c2,dB and friends) ---
struct HeadCore {
    float er[2], ei[2], qr[2], qi[2], ur[2], ui[2], c2r[2], c2i[2];
    float xr0[2], xi0[2];   // dB
};

__device__ __forceinline__ void head_setup(
    const float* __restrict__ Ar, const float* __restrict__ Ai,
    const float* __restrict__ Br, const float* __restrict__ Bi,
    const float* __restrict__ Pr, const float* __restrict__ Pi,
    const float* __restrict__ Cr, const float* __restrict__ Ci,
    const float* __restrict__ logdt, int h, int lane, HeadCore& C)
{
    const int base = h * 64 + lane;
    const float dt  = expf(logdt[h]);
    const float del = 0.5f * dt;

    float pr[2], pi[2], d_r[2], d_i[2], mmr[2], mmi[2];
    float red4[4] = {0.f, 0.f, 0.f, 0.f};
    #pragma unroll
    for (int s = 0; s < 2; ++s) {
        const int n = base + 32 * s;
        const float lr = -Ar[n], li = -Ai[n];
        const float ar = 1.f + del * lr, ai = del * li;
        const float mr = 1.f - del * lr, mi = -del * li;
        const float idm = 1.f / (mr * mr + mi * mi);
        d_r[s] = mr * idm; d_i[s] = -mi * idm;
        pr[s] = Pr[n]; pi[s] = Pi[n];
        C.er[s] = d_r[s] * ar - d_i[s] * ai;
        C.ei[s] = d_r[s] * ai + d_i[s] * ar;
        C.qr[s] = d_r[s] * pr[s] - d_i[s] * pi[s];
        C.qi[s] = d_r[s] * pi[s] + d_i[s] * pr[s];
        C.c2r[s] = 2.f * Cr[n]; C.c2i[s] = 2.f * Ci[n];
        const float pp = pr[s] * pr[s] + pi[s] * pi[s];
        red4[0] += d_r[s] * pp; red4[1] += d_i[s] * pp;
        const float zr = dt * Br[n], zi = dt * Bi[n];
        mmr[s] = d_r[s] * zr - d_i[s] * zi;
        mmi[s] = d_r[s] * zi + d_i[s] * zr;
        red4[2] += pr[s] * mmr[s] + pi[s] * mmi[s];
        red4[3] += pr[s] * mmi[s] - pi[s] * mmr[s];
    }
    #pragma unroll
    for (int o = 16; o; o >>= 1)
        #pragma unroll
        for (int k = 0; k < 4; ++k)
            red4[k] += __shfl_xor_sync(0xffffffffu, red4[k], o);

    const float wr0 = 1.f + del * red4[0], wi0 = del * red4[1];
    const float iw = 1.f / (wr0 * wr0 + wi0 * wi0);
    const float gar = del * wr0 * iw, gai = -del * wi0 * iw;
    const float dkr = del * red4[0], dki = del * red4[1];
    const float alr = del - (gar * dkr - gai * dki);
    const float ali = -(gar * dki + gai * dkr);

    #pragma unroll
    for (int s = 0; s < 2; ++s) {
        const float gr2 = pr[s] * C.er[s] + pi[s] * C.ei[s];
        const float gi2 = pr[s] * C.ei[s] - pi[s] * C.er[s];
        C.ur[s] = alr * pr[s] + ali * pi[s] + gar * gr2 - gai * gi2;
        C.ui[s] = -alr * pi[s] + ali * pr[s] + gar * gi2 + gai * gr2;
    }
    const float gtr = gar * red4[2] - gai * red4[3];
    const float gti = gar * red4[3] + gai * red4[2];
    #pragma unroll
    for (int s = 0; s < 2; ++s) {
        C.xr0[s] = mmr[s] - (gtr * C.qr[s] - gti * C.qi[s]);
        C.xi0[s] = mmi[s] - (gtr * C.qi[s] + gti * C.qr[s]);
    }
}

// =================== K1: state-only checkpoint kernel (T=16) =================
#define T1 16

__global__ __launch_bounds__(64, 1) void ssm_state_kernel(
    const float* __restrict__ Ar, const float* __restrict__ Ai,
    const float* __restrict__ Br, const float* __restrict__ Bi,
    const float* __restrict__ Pr, const float* __restrict__ Pi,
    const float* __restrict__ Cr, const float* __restrict__ Ci,
    const float* __restrict__ logdt,
    int H, int NB1, int Kblk)
{
    __shared__ __align__(16) float s_part[2][32 * ROWP2];
    __shared__ __align__(16) u64 s_dup[2][32];

    const int wip = threadIdx.x >> 5;
    const int lane = threadIdx.x & 31;
    const int h = blockIdx.x * 2 + wip;
    if (h >= H) return;

    HeadCore C;
    head_setup(Ar, Ai, Br, Bi, Pr, Pi, Cr, Ci, logdt, h, lane, C);

    // powers m=0..T1-1
    float qer[T1][2], qei[T1][2], uer[T1][2], uei[T1][2];
    float eTr[2], eTi[2];
    {
        float emr[2] = {1.f, 1.f}, emi[2] = {0.f, 0.f};
        #pragma unroll
        for (int m = 0; m < T1; ++m) {
            #pragma unroll
            for (int s = 0; s < 2; ++s) {
                qer[m][s] = C.qr[s] * emr[s] - C.qi[s] * emi[s];
                qei[m][s] = C.qr[s] * emi[s] + C.qi[s] * emr[s];
                uer[m][s] = C.ur[s] * emr[s] - C.ui[s] * emi[s];
                uei[m][s] = C.ur[s] * emi[s] + C.ui[s] * emr[s];
                const float t2 = emr[s] * C.er[s] - emi[s] * C.ei[s];
                emi[s] = emr[s] * C.ei[s] + emi[s] * C.er[s];
                emr[s] = t2;
            }
        }
        eTr[0] = emr[0]; eTi[0] = emi[0]; eTr[1] = emr[1]; eTi[1] = emi[1];
    }

    // nu_m = u^T E^m q, m=0..T1-2
    float red[2 * (T1 - 1)];
    #pragma unroll
    for (int m = 0; m < T1 - 1; ++m) {
        float a = 0.f, b = 0.f;
        #pragma unroll
        for (int s = 0; s < 2; ++s) {
            a += C.ur[s] * qer[m][s] - C.ui[s] * qei[m][s];
            b += C.ur[s] * qei[m][s] + C.ui[s] * qer[m][s];
        }
        red[2 * m] = a; red[2 * m + 1] = b;
    }
    #pragma unroll
    for (int o = 16; o; o >>= 1)
        #pragma unroll
        for (int k = 0; k < 2 * (T1 - 1); ++k)
            red[k] += __shfl_xor_sync(0xffffffffu, red[k], o);

    // beta = power-series inverse of (1 + z*nu)
    float btr[T1], bti[T1];
    btr[0] = 1.f; bti[0] = 0.f;
    #pragma unroll
    for (int m = 1; m < T1; ++m) {
        float a = 0.f, b = 0.f;
        #pragma unroll
        for (int j = 0; j < m; ++j) {
            const float nr = red[2 * (m - 1 - j)], ni = red[2 * (m - 1 - j) + 1];
            a -= nr * btr[j] - ni * bti[j];
            b -= nr * bti[j] + ni * btr[j];
        }
        btr[m] = a; bti[m] = b;
    }

    // R_i = sum_{j>=i} beta_{j-i} E^{T1-1-j} q ; store negation-free packed
    u64 RrN[T1], RiP[T1], RiN[T1];
    #pragma unroll
    for (int i = 0; i < T1; ++i) {
        float rr[2] = {0.f, 0.f}, ri[2] = {0.f, 0.f};
        #pragma unroll
        for (int j = i; j < T1; ++j) {
            const float br2 = btr[j - i], bi2 = bti[j - i];
            #pragma unroll
            for (int s = 0; s < 2; ++s) {
                rr[s] += br2 * qer[T1 - 1 - j][s] - bi2 * qei[T1 - 1 - j][s];
                ri[s] += br2 * qei[T1 - 1 - j][s] + bi2 * qer[T1 - 1 - j][s];
            }
        }
        RrN[i] = pk(-rr[0], -rr[1]);
        RiP[i] = pk(ri[0], ri[1]);
        RiN[i] = pk(-ri[0], -ri[1]);
    }

    u64 UEr[T1], UEi[T1];
    #pragma unroll
    for (int m = 0; m < T1; ++m) {
        UEr[m] = pk(uer[m][0], uer[m][1]);
        UEi[m] = pk(uei[m][0], uei[m][1]);
    }
    const u64 ETr = pk(eTr[0], eTr[1]);
    const u64 ETi = pk(eTi[0], eTi[1]);
    const u64 NEG1 = pk(-1.f, -1.f);
    const u64 ZERO = pk(0.f, 0.f);

    u64 Xr = pk(C.xr0[0], C.xr0[1]);
    u64 Xi = pk(C.xi0[0], C.xi0[1]);

    float* const sp = &s_part[wip][0];
    u64* const sd = &s_dup[wip][0];
    const ulonglong2* const rowp =
        reinterpret_cast<const ulonglong2*>(sp + lane * ROWP2);
    const ulonglong2* const dpr = reinterpret_cast<const ulonglong2*>(sd);
    const ulonglong2* const dpi = reinterpret_cast<const ulonglong2*>(sd + 16);

    #pragma unroll 1
    for (int b = 0; b < NB1; ++b) {
        const u64 XiN = f2mul(Xi, NEG1);
        // mu dots -> u64 scatter: rows m (mur partials), 16+m (mui partials)
        #pragma unroll
        for (int m = 0; m < T1; ++m) {
            const u64 ar = f2fma(UEi[m], XiN, f2mul(UEr[m], Xr));
            const u64 br = f2fma(UEi[m], Xr,  f2mul(UEr[m], Xi));
            *reinterpret_cast<u64*>(sp + m * ROWP2 + 2 * lane) = ar;
            *reinterpret_cast<u64*>(sp + (16 + m) * ROWP2 + 2 * lane) = br;
        }
        __syncwarp();
        // rowsum: lane sums row 'lane' (64 floats = 32 u64)
        {
            u64 acc[8];
            #pragma unroll
            for (int j = 0; j < 8; ++j) {
                const ulonglong2 v0 = rowp[j], v1 = rowp[8 + j];
                acc[j] = f2add(f2add(v0.x, v0.y), f2add(v1.x, v1.y));
            }
            u64 t0 = f2add(f2add(acc[0], acc[1]), f2add(acc[2], acc[3]));
            u64 t1 = f2add(f2add(acc[4], acc[5]), f2add(acc[6], acc[7]));
            const float2 f = up(f2add(t0, t1));
            const float rs = f.x + f.y;
            sd[lane] = pk(rs, rs);
        }
        __syncwarp();
        // update: X' = E^T1.*X - sum_i mu_i.*R_i  (negation-free, 4+4 chains)
        {
            u64 A0 = f2fma(ETi, XiN, f2mul(ETr, Xr));
            u64 B0 = f2fma(ETi, Xr,  f2mul(ETr, Xi));
            u64 A1 = ZERO, A2 = ZERO, A3 = ZERO;
            u64 B1 = ZERO, B2 = ZERO, B3 = ZERO;
            #pragma unroll
            for (int j = 0; j < 8; ++j) {
                const ulonglong2 mr2 = dpr[j];
                const ulonglong2 mi2 = dpi[j];
                const int i0 = 2 * j, i1 = 2 * j + 1;
                if ((j & 1) == 0) {
                    A0 = f2fma(mr2.x, RrN[i0], f2fma(mi2.x, RiP[i0], A0));
                    B0 = f2fma(mr2.x, RiN[i0], f2fma(mi2.x, RrN[i0], B0));
                    A1 = f2fma(mr2.y, RrN[i1], f2fma(mi2.y, RiP[i1], A1));
                    B1 = f2fma(mr2.y, RiN[i1], f2fma(mi2.y, RrN[i1], B1));
                } else {
                    A2 = f2fma(mr2.x, RrN[i0], f2fma(mi2.x, RiP[i0], A2));
                    B2 = f2fma(mr2.x, RiN[i0], f2fma(mi2.x, RrN[i0], B2));
                    A3 = f2fma(mr2.y, RrN[i1], f2fma(mi2.y, RiP[i1], A3));
                    B3 = f2fma(mr2.y, RiN[i1], f2fma(mi2.y, RrN[i1], B3));
                }
            }
            Xr = f2add(f2add(A0, A1), f2add(A2, A3));
            Xi = f2add(f2add(B0, B1), f2add(B2, B3));
        }
        // checkpoint every Kblk blocks
        if (((b + 1) % Kblk) == 0) {
            const int c = (b + 1) / Kblk;
            const float2 a = up(Xr), b2 = up(Xi);
            *reinterpret_cast<float4*>(
                &g_ckpt[(h * NCC + c) * 128 + lane * 4]) =
                make_float4(a.x, a.y, b2.x, b2.y);
        }
    }
}

// =================== K2: chunk output kernel (T=8, full) =====================
#define T2 8

__global__ __launch_bounds__(128, 1) void ssm_out_kernel(
    const float* __restrict__ Ar, const float* __restrict__ Ai,
    const float* __restrict__ Br, const float* __restrict__ Bi,
    const float* __restrict__ Pr, const float* __restrict__ Pi,
    const float* __restrict__ Cr, const float* __restrict__ Ci,
    const float* __restrict__ logdt,
    float* __restrict__ out, int H, int L, int NC, int K)
{
    __shared__ __align__(16) float s_part[4][24 * ROWP2];
    __shared__ __align__(16) u64 s_dup[4][24];

    const int wip = threadIdx.x >> 5;
    const int lane = threadIdx.x & 31;
    const int g = blockIdx.x * 4 + wip;
    if (g >= H * NC) return;
    const int h = g / NC;
    const int c = g % NC;

    HeadCore Cc;
    head_setup(Ar, Ai, Br, Bi, Pr, Pi, Cr, Ci, logdt, h, lane, Cc);

    // powers m=0..T2-1
    float qer[T2][2], qei[T2][2], uer[T2][2], uei[T2][2], cer[T2][2], cei[T2][2];
    float eTr[2], eTi[2];
    {
        float emr[2] = {1.f, 1.f}, emi[2] = {0.f, 0.f};
        #pragma unroll
        for (int m = 0; m < T2; ++m) {
            #pragma unroll
            for (int s = 0; s < 2; ++s) {
                qer[m][s] = Cc.qr[s] * emr[s] - Cc.qi[s] * emi[s];
                qei[m][s] = Cc.qr[s] * emi[s] + Cc.qi[s] * emr[s];
                uer[m][s] = Cc.ur[s] * emr[s] - Cc.ui[s] * emi[s];
                uei[m][s] = Cc.ur[s] * emi[s] + Cc.ui[s] * emr[s];
                cer[m][s] = Cc.c2r[s] * emr[s] - Cc.c2i[s] * emi[s];
                cei[m][s] = Cc.c2r[s] * emi[s] + Cc.c2i[s] * emr[s];
                const float t2 = emr[s] * Cc.er[s] - emi[s] * Cc.ei[s];
                emi[s] = emr[s] * Cc.ei[s] + emi[s] * Cc.er[s];
                emr[s] = t2;
            }
        }
        eTr[0] = emr[0]; eTi[0] = emi[0]; eTr[1] = emr[1]; eTi[1] = emi[1];
    }

    // nu, eta reductions
    float red[4 * (T2 - 1)];
    #pragma unroll
    for (int m = 0; m < T2 - 1; ++m) {
        float a = 0.f, b = 0.f, cc = 0.f, d = 0.f;
        #pragma unroll
        for (int s = 0; s < 2; ++s) {
            a  += Cc.ur[s] * qer[m][s] - Cc.ui[s] * qei[m][s];
            b  += Cc.ur[s] * qei[m][s] + Cc.ui[s] * qer[m][s];
            cc += Cc.c2r[s] * qer[m][s] - Cc.c2i[s] * qei[m][s];
            d  += Cc.c2r[s] * qei[m][s] + Cc.c2i[s] * qer[m][s];
        }
        red[4 * m] = a; red[4 * m + 1] = b; red[4 * m + 2] = cc; red[4 * m + 3] = d;
    }
    #pragma unroll
    for (int o = 16; o; o >>= 1)
        #pragma unroll
        for (int k = 0; k < 4 * (T2 - 1); ++k)
            red[k] += __shfl_xor_sync(0xffffffffu, red[k], o);

    float btr[T2], bti[T2];
    btr[0] = 1.f; bti[0] = 0.f;
    #pragma unroll
    for (int m = 1; m < T2; ++m) {
        float a = 0.f, b = 0.f;
        #pragma unroll
        for (int j = 0; j < m; ++j) {
            const float nr = red[4 * (m - 1 - j)], ni = red[4 * (m - 1 - j) + 1];
            a -= nr * btr[j] - ni * bti[j];
            b -= nr * bti[j] + ni * btr[j];
        }
        btr[m] = a; bti[m] = b;
    }
    float wcr[T2 - 1], wci[T2 - 1];
    #pragma unroll
    for (int m = 0; m < T2 - 1; ++m) {
        float a = 0.f, b = 0.f;
        #pragma unroll
        for (int j = 0; j <= m; ++j) {
            const float er2 = red[4 * j + 2], ei2 = red[4 * j + 3];
            a += er2 * btr[m - j] - ei2 * bti[m - j];
            b += er2 * bti[m - j] + ei2 * btr[m - j];
        }
        wcr[m] = a; wci[m] = b;
    }

    u64 RrN[T2], RiP[T2], RiN[T2];
    #pragma unroll
    for (int i = 0; i < T2; ++i) {
        float rr[2] = {0.f, 0.f}, ri[2] = {0.f, 0.f};
        #pragma unroll
        for (int j = i; j < T2; ++j) {
            const float br2 = btr[j - i], bi2 = bti[j - i];
            #pragma unroll
            for (int s = 0; s < 2; ++s) {
                rr[s] += br2 * qer[T2 - 1 - j][s] - bi2 * qei[T2 - 1 - j][s];
                ri[s] += br2 * qei[T2 - 1 - j][s] + bi2 * qer[T2 - 1 - j][s];
            }
        }
        RrN[i] = pk(-rr[0], -rr[1]);
        RiP[i] = pk(ri[0], ri[1]);
        RiN[i] = pk(-ri[0], -ri[1]);
    }

    u64 UEr[T2], UEi[T2], CEr[T2], CEi[T2];
    #pragma unroll
    for (int m = 0; m < T2; ++m) {
        UEr[m] = pk(uer[m][0], uer[m][1]);
        UEi[m] = pk(uei[m][0], uei[m][1]);
        CEr[m] = pk(cer[m][0], cer[m][1]);
        CEi[m] = pk(cei[m][0], cei[m][1]);
    }
    const u64 ETr = pk(eTr[0], eTr[1]);
    const u64 ETi = pk(eTi[0], eTi[1]);
    const u64 NEG1 = pk(-1.f, -1.f);
    const u64 ZERO = pk(0.f, 0.f);

    // initial state for this chunk
    u64 Xr, Xi;
    if (c == 0) {
        Xr = pk(Cc.xr0[0], Cc.xr0[1]);
        Xi = pk(Cc.xi0[0], Cc.xi0[1]);
    } else {
        const float4 xv = *reinterpret_cast<const float4*>(
            &g_ckpt[(h * NCC + c) * 128 + lane * 4]);
        Xr = pk(xv.x, xv.y);
        Xi = pk(xv.z, xv.w);
    }

    const int len = (c == NC - 1) ? (L - c * K) : K;
    const int NB2 = len / T2;
    float* __restrict__ o_ptr = out + (long)h * L + (long)c * K;

    float* const sp = &s_part[wip][0];
    u64* const sd = &s_dup[wip][0];
    const int row = (lane < 24) ? lane : (lane - 24);
    const ulonglong2* const rowp =
        reinterpret_cast<const ulonglong2*>(sp + row * ROWP2);
    const ulonglong2* const dpr = reinterpret_cast<const ulonglong2*>(sd);
    const ulonglong2* const dpi = reinterpret_cast<const ulonglong2*>(sd + 8);
    const float* const sdf = reinterpret_cast<const float*>(sd);

    // per-lane premasked conv coefficients (lane handles output mo = lane&7)
    const int mo = lane & 7;
    float mwr[T2 - 1], mwi[T2 - 1];
    int mix0[T2 - 1], mix1[T2 - 1];
    #pragma unroll
    for (int d = 0; d < T2 - 1; ++d) {
        const bool act = d < mo;
        const int idx = act ? (mo - 1 - d) : 0;
        mwr[d] = act ? -wcr[d] : 0.f;
        mwi[d] = act ? wci[d] : 0.f;
        mix0[d] = idx * 2;            // float index of mur_idx (low half of dup)
        mix1[d] = (8 + idx) * 2;      // float index of mui_idx
    }
    const bool do_store = (lane < 8);

    #pragma unroll 1
    for (int b = 0; b < NB2; ++b) {
        const u64 XiN = f2mul(Xi, NEG1);
        // dots -> u64 scatter: rows m (mur), 8+m (mui), 16+m (kap)
        #pragma unroll
        for (int m = 0; m < T2; ++m) {
            const u64 ar = f2fma(UEi[m], XiN, f2mul(UEr[m], Xr));
            const u64 br = f2fma(UEi[m], Xr,  f2mul(UEr[m], Xi));
            const u64 cr = f2fma(CEi[m], XiN, f2mul(CEr[m], Xr));
            *reinterpret_cast<u64*>(sp + m * ROWP2 + 2 * lane) = ar;
            *reinterpret_cast<u64*>(sp + (8 + m) * ROWP2 + 2 * lane) = br;
            *reinterpret_cast<u64*>(sp + (16 + m) * ROWP2 + 2 * lane) = cr;
        }
        __syncwarp();
        // rowsum (lanes 24-31 duplicate rows 0-7)
        {
            u64 acc[8];
            #pragma unroll
            for (int j = 0; j < 8; ++j) {
                const ulonglong2 v0 = rowp[j], v1 = rowp[8 + j];
                acc[j] = f2add(f2add(v0.x, v0.y), f2add(v1.x, v1.y));
            }
            u64 t0 = f2add(f2add(acc[0], acc[1]), f2add(acc[2], acc[3]));
            u64 t1 = f2add(f2add(acc[4], acc[5]), f2add(acc[6], acc[7]));
            const float2 f = up(f2add(t0, t1));
            const float rs = f.x + f.y;
            sd[row] = pk(rs, rs);   // lanes 24-31 rewrite rows 0-7 (same value)
        }
        __syncwarp();
        // update (negation-free, 2+2 chains)
        {
            u64 A0 = f2fma(ETi, XiN, f2mul(ETr, Xr));
            u64 B0 = f2fma(ETi, Xr,  f2mul(ETr, Xi));
            u64 A1 = ZERO, B1 = ZERO;
            #pragma unroll
            for (int j = 0; j < 4; ++j) {
                const ulonglong2 mr2 = dpr[j];
                const ulonglong2 mi2 = dpi[j];
                const int i0 = 2 * j, i1 = 2 * j + 1;
                A0 = f2fma(mr2.x, RrN[i0], f2fma(mi2.x, RiP[i0], A0));
                B0 = f2fma(mr2.x, RiN[i0], f2fma(mi2.x, RrN[i0], B0));
                A1 = f2fma(mr2.y, RrN[i1], f2fma(mi2.y, RiP[i1], A1));
                B1 = f2fma(mr2.y, RiN[i1], f2fma(mi2.y, RrN[i1], B1));
            }
            Xr = f2add(A0, A1);
            Xi = f2add(B0, B1);
        }
        // outputs: masked conv on broadcast scalars, predicated store
        {
            float kv = sdf[(16 + mo) * 2];
            #pragma unroll
            for (int d = 0; d < T2 - 1; ++d)
                kv = fmaf(mwr[d], sdf[mix0[d]], fmaf(mwi[d], sdf[mix1[d]], kv));
            if (do_store) o_ptr[b * T2 + mo] = kv;
        }
    }

    // scalar tail (only possible in last chunk when L % 8 != 0)
    for (int l = NB2 * T2; l < len; ++l) {
        float2 xr2 = up(Xr), xi2 = up(Xi);
        float xrr[2] = {xr2.x, xr2.y}, xii[2] = {xi2.x, xi2.y};
        float sr2 = 0.f, si2 = 0.f, kv = 0.f;
        #pragma unroll
        for (int s = 0; s < 2; ++s) {
            sr2 += Cc.ur[s] * xrr[s] - Cc.ui[s] * xii[s];
            si2 += Cc.ur[s] * xii[s] + Cc.ui[s] * xrr[s];
            kv  += Cc.c2r[s] * xrr[s] - Cc.c2i[s] * xii[s];
        }
        sr2 = wsum(sr2); si2 = wsum(si2); kv = wsum(kv);
        if (lane == 0) o_ptr[l] = kv;
        float nxr[2], nxi[2];
        #pragma unroll
        for (int s = 0; s < 2; ++s) {
            nxr[s] = Cc.er[s] * xrr[s] - Cc.ei[s] * xii[s]
                   - (sr2 * Cc.qr[s] - si2 * Cc.qi[s]);
            nxi[s] = Cc.er[s] * xii[s] + Cc.ei[s] * xrr[s]
                   - (sr2 * Cc.qi[s] + si2 * Cc.qr[s]);
        }
        Xr = pk(nxr[0], nxr[1]); Xi = pk(nxi[0], nxi[1]);
    }
}

extern "C" void kernel_launch(void* const* d_in, const int* in_sizes, int n_in,
                              void* d_out, int out_size) {
    const float* Ar = (const float*)d_in[0];
    const float* Ai = (const float*)d_in[1];
    const float* Br = (const float*)d_in[2];
    const float* Bi = (const float*)d_in[3];
    const float* Pr = (const float*)d_in[4];
    const float* Pi = (const float*)d_in[5];
    const float* Cr = (const float*)d_in[6];
    const float* Ci = (const float*)d_in[7];
    const float* ld = (const float*)d_in[8];
    float* out = (float*)d_out;

    const int H = in_sizes[8];          // 256
    const int L = out_size / H;         // 2048

    int NC = NCC;                       // 8 chunks
    int K = L / NC;
    const bool chunky = (H <= 256) && (L % NC == 0) && (K % T1 == 0);
    if (!chunky) { NC = 1; K = L; }

    if (NC > 1) {
        const int Kblk = K / T1;                 // blocks per chunk in K1
        const int NB1 = (NC - 1) * Kblk;         // total K1 blocks
        ssm_state_kernel<<<(H + 1) / 2, 64>>>(
            Ar, Ai, Br, Bi, Pr, Pi, Cr, Ci, ld, H, NB1, Kblk);
    }
    const int nwarps = H * NC;
    ssm_out_kernel<<<(nwarps + 3) / 4, 128>>>(
        Ar, Ai, Br, Bi, Pr, Pi, Cr, Ci, ld, out, H, L, NC, K);
}

// round 10
// speedup vs baseline: 1.0976x; 1.0976x over previous
#include <cuda_runtime.h>

// S4/DPLR kernel materialization, H=256, N2=64, RANK=1, CH=1, L=2048.
// Single-pass, one warp per head, T=16 blocked rank-1 Woodbury recurrence
// with linear recombination. Register budget: UE + R packed constants in
// registers, CE per-lane in shared memory. Scalar-fold scatter, branchless
// rowsum/dup/conv, negation-free 4-chain update. 2 warps (heads) per CTA.

#define T 16
#define ROWP 36   // floats per 32-float padded row

typedef unsigned long long u64;

__device__ __forceinline__ float wsum(float v) {
    #pragma unroll
    for (int o = 16; o; o >>= 1) v += __shfl_xor_sync(0xffffffffu, v, o);
    return v;
}
__device__ __forceinline__ u64 pk(float x, float y) {
    u64 r; asm("mov.b64 %0,{%1,%2};" : "=l"(r) : "f"(x), "f"(y)); return r;
}
__device__ __forceinline__ float2 up(u64 a) {
    float2 v; asm("mov.b64 {%0,%1},%2;" : "=f"(v.x), "=f"(v.y) : "l"(a)); return v;
}
__device__ __forceinline__ u64 f2fma(u64 a, u64 b, u64 c) {
    u64 d; asm("fma.rn.f32x2 %0,%1,%2,%3;" : "=l"(d) : "l"(a), "l"(b), "l"(c)); return d;
}
__device__ __forceinline__ u64 f2mul(u64 a, u64 b) {
    u64 d; asm("mul.rn.f32x2 %0,%1,%2;" : "=l"(d) : "l"(a), "l"(b)); return d;
}
__device__ __forceinline__ u64 f2add(u64 a, u64 b) {
    u64 d; asm("add.rn.f32x2 %0,%1,%2;" : "=l"(d) : "l"(a), "l"(b)); return d;
}

struct HeadCore {
    float er[2], ei[2], qr[2], qi[2], ur[2], ui[2], c2r[2], c2i[2];
    float xr0[2], xi0[2];
};

__device__ __forceinline__ void head_setup(
    const float* __restrict__ Ar, const float* __restrict__ Ai,
    const float* __restrict__ Br, const float* __restrict__ Bi,
    const float* __restrict__ Pr, const float* __restrict__ Pi,
    const float* __restrict__ Cr, const float* __restrict__ Ci,
    const float* __restrict__ logdt, int h, int lane, HeadCore& C)
{
    const int base = h * 64 + lane;
    const float dt  = expf(logdt[h]);
    const float del = 0.5f * dt;

    float pr[2], pi[2], d_r[2], d_i[2], mmr[2], mmi[2];
    float red4[4] = {0.f, 0.f, 0.f, 0.f};
    #pragma unroll
    for (int s = 0; s < 2; ++s) {
        const int n = base + 32 * s;
        const float lr = -Ar[n], li = -Ai[n];
        const float ar = 1.f + del * lr, ai = del * li;
        const float mr = 1.f - del * lr, mi = -del * li;
        const float idm = 1.f / (mr * mr + mi * mi);
        d_r[s] = mr * idm; d_i[s] = -mi * idm;
        pr[s] = Pr[n]; pi[s] = Pi[n];
        C.er[s] = d_r[s] * ar - d_i[s] * ai;
        C.ei[s] = d_r[s] * ai + d_i[s] * ar;
        C.qr[s] = d_r[s] * pr[s] - d_i[s] * pi[s];
        C.qi[s] = d_r[s] * pi[s] + d_i[s] * pr[s];
        C.c2r[s] = 2.f * Cr[n]; C.c2i[s] = 2.f * Ci[n];
        const float pp = pr[s] * pr[s] + pi[s] * pi[s];
        red4[0] += d_r[s] * pp; red4[1] += d_i[s] * pp;
        const float zr = dt * Br[n], zi = dt * Bi[n];
        mmr[s] = d_r[s] * zr - d_i[s] * zi;
        mmi[s] = d_r[s] * zi + d_i[s] * zr;
        red4[2] += pr[s] * mmr[s] + pi[s] * mmi[s];
        red4[3] += pr[s] * mmi[s] - pi[s] * mmr[s];
    }
    #pragma unroll
    for (int o = 16; o; o >>= 1)
        #pragma unroll
        for (int k = 0; k < 4; ++k)
            red4[k] += __shfl_xor_sync(0xffffffffu, red4[k], o);

    const float wr0 = 1.f + del * red4[0], wi0 = del * red4[1];
    const float iw = 1.f / (wr0 * wr0 + wi0 * wi0);
    const float gar = del * wr0 * iw, gai = -del * wi0 * iw;
    const float dkr = del * red4[0], dki = del * red4[1];
    const float alr = del - (gar * dkr - gai * dki);
    const float ali = -(gar * dki + gai * dkr);

    #pragma unroll
    for (int s = 0; s < 2; ++s) {
        const float gr2 = pr[s] * C.er[s] + pi[s] * C.ei[s];
        const float gi2 = pr[s] * C.ei[s] - pi[s] * C.er[s];
        C.ur[s] = alr * pr[s] + ali * pi[s] + gar * gr2 - gai * gi2;
        C.ui[s] = -alr * pi[s] + ali * pr[s] + gar * gi2 + gai * gr2;
    }
    const float gtr = gar * red4[2] - gai * red4[3];
    const float gti = gar * red4[3] + gai * red4[2];
    #pragma unroll
    for (int s = 0; s < 2; ++s) {
        C.xr0[s] = mmr[s] - (gtr * C.qr[s] - gti * C.qi[s]);
        C.xi0[s] = mmi[s] - (gtr * C.qi[s] + gti * C.qr[s]);
    }
}

__global__ __launch_bounds__(64, 1) void ssm_dplr_kernel(
    const float* __restrict__ Ar, const float* __restrict__ Ai,
    const float* __restrict__ Br, const float* __restrict__ Bi,
    const float* __restrict__ Pr, const float* __restrict__ Pi,
    const float* __restrict__ Cr, const float* __restrict__ Ci,
    const float* __restrict__ logdt,
    float* __restrict__ out, int H, int L)
{
    // per-warp buffers (2 warps = 2 heads per CTA)
    __shared__ __align__(16) float s_part[2][48 * ROWP];       // 48 rows x 32fl
    __shared__ __align__(16) ulonglong2 s_pair[2][16];         // (murN, muiP)
    __shared__ __align__(16) u64 s_aux[2][32];                 // [0:16) kap dup, [16:32) muiN
    __shared__ __align__(16) ulonglong2 s_cel[2][T][32];       // per-lane (CEr, CEi)

    const int wip = threadIdx.x >> 5;
    const int lane = threadIdx.x & 31;
    const int h = blockIdx.x * 2 + wip;
    if (h >= H) return;

    HeadCore C;
    head_setup(Ar, Ai, Br, Bi, Pr, Pi, Cr, Ci, logdt, h, lane, C);

    // powers m=0..T-1: UE regs, CE -> smem, q powers kept for R build
    float qer[T][2], qei[T][2];
    u64 UEr[T], UEi[T];
    float eTr[2], eTi[2];
    {
        float emr[2] = {1.f, 1.f}, emi[2] = {0.f, 0.f};
        #pragma unroll
        for (int m = 0; m < T; ++m) {
            float uer[2], uei[2], cer[2], cei[2];
            #pragma unroll
            for (int s = 0; s < 2; ++s) {
                qer[m][s] = C.qr[s] * emr[s] - C.qi[s] * emi[s];
                qei[m][s] = C.qr[s] * emi[s] + C.qi[s] * emr[s];
                uer[s] = C.ur[s] * emr[s] - C.ui[s] * emi[s];
                uei[s] = C.ur[s] * emi[s] + C.ui[s] * emr[s];
                cer[s] = C.c2r[s] * emr[s] - C.c2i[s] * emi[s];
                cei[s] = C.c2r[s] * emi[s] + C.c2i[s] * emr[s];
                const float t2 = emr[s] * C.er[s] - emi[s] * C.ei[s];
                emi[s] = emr[s] * C.ei[s] + emi[s] * C.er[s];
                emr[s] = t2;
            }
            UEr[m] = pk(uer[0], uer[1]);
            UEi[m] = pk(uei[0], uei[1]);
            s_cel[wip][m][lane] =
                make_ulonglong2(pk(cer[0], cer[1]), pk(cei[0], cei[1]));
        }
        eTr[0] = emr[0]; eTi[0] = emi[0]; eTr[1] = emr[1]; eTi[1] = emi[1];
    }
    __syncwarp();

    // nu_m, eta_m for m=0..T-2
    float red[4 * (T - 1)];
    #pragma unroll
    for (int m = 0; m < T - 1; ++m) {
        float a = 0.f, b = 0.f, cc = 0.f, d = 0.f;
        float uer[2], uei[2];
        const float2 u0 = up(UEr[0]);   // unused; keep u from HeadCore
        (void)u0;
        #pragma unroll
        for (int s = 0; s < 2; ++s) {
            a  += C.ur[s] * qer[m][s] - C.ui[s] * qei[m][s];
            b  += C.ur[s] * qei[m][s] + C.ui[s] * qer[m][s];
            cc += C.c2r[s] * qer[m][s] - C.c2i[s] * qei[m][s];
            d  += C.c2r[s] * qei[m][s] + C.c2i[s] * qer[m][s];
        }
        (void)uer; (void)uei;
        red[4 * m] = a; red[4 * m + 1] = b; red[4 * m + 2] = cc; red[4 * m + 3] = d;
    }
    #pragma unroll
    for (int o = 16; o; o >>= 1)
        #pragma unroll
        for (int k = 0; k < 4 * (T - 1); ++k)
            red[k] += __shfl_xor_sync(0xffffffffu, red[k], o);

    // beta = (1 + z*nu)^{-1}
    float btr[T], bti[T];
    btr[0] = 1.f; bti[0] = 0.f;
    #pragma unroll
    for (int m = 1; m < T; ++m) {
        float a = 0.f, b = 0.f;
        #pragma unroll
        for (int j = 0; j < m; ++j) {
            const float nr = red[4 * (m - 1 - j)], ni = red[4 * (m - 1 - j) + 1];
            a -= nr * btr[j] - ni * bti[j];
            b -= nr * bti[j] + ni * btr[j];
        }
        btr[m] = a; bti[m] = b;
    }
    // w = eta (*) beta
    float wcr[T - 1], wci[T - 1];
    #pragma unroll
    for (int m = 0; m < T - 1; ++m) {
        float a = 0.f, b = 0.f;
        #pragma unroll
        for (int j = 0; j <= m; ++j) {
            const float er2 = red[4 * j + 2], ei2 = red[4 * j + 3];
            a += er2 * btr[m - j] - ei2 * bti[m - j];
            b += er2 * bti[m - j] + ei2 * btr[m - j];
        }
        wcr[m] = a; wci[m] = b;
    }

    // R_i = sum_{j>=i} beta_{j-i} E^{T-1-j} q   (positive, packed)
    u64 RrP[T], RiP[T];
    #pragma unroll
    for (int i = 0; i < T; ++i) {
        float rr[2] = {0.f, 0.f}, ri[2] = {0.f, 0.f};
        #pragma unroll
        for (int j = i; j < T; ++j) {
            const float br2 = btr[j - i], bi2 = bti[j - i];
            #pragma unroll
            for (int s = 0; s < 2; ++s) {
                rr[s] += br2 * qer[T - 1 - j][s] - bi2 * qei[T - 1 - j][s];
                ri[s] += br2 * qei[T - 1 - j][s] + bi2 * qer[T - 1 - j][s];
            }
        }
        RrP[i] = pk(rr[0], rr[1]);
        RiP[i] = pk(ri[0], ri[1]);
    }

    const u64 ETr = pk(eTr[0], eTr[1]);
    const u64 ETi = pk(eTi[0], eTi[1]);
    const u64 NEG1 = pk(-1.f, -1.f);
    const u64 ZERO = pk(0.f, 0.f);

    u64 Xr = pk(C.xr0[0], C.xr0[1]);
    u64 Xi = pk(C.xi0[0], C.xi0[1]);

    float* __restrict__ o_ptr = out + (long)h * L;
    const int NB = L / T;
    const int Lb = NB * T;

    float* const sp = &s_part[wip][0];
    u64* const su_pair = reinterpret_cast<u64*>(&s_pair[wip][0]);
    u64* const su_aux = &s_aux[wip][0];
    const float* const pf = reinterpret_cast<const float*>(&s_pair[wip][0]);
    const float* const af = reinterpret_cast<const float*>(&s_aux[wip][0]);

    // rowsum assignments: row1 = lane (mur 0-15 / mui 0-15), row2 = 32+(lane&15) kap
    const ulonglong2* const row1p =
        reinterpret_cast<const ulonglong2*>(sp + lane * ROWP);
    const ulonglong2* const row2p =
        reinterpret_cast<const ulonglong2*>(sp + (32 + (lane & 15)) * ROWP);
    // merged dup-store addressing
    const int idx1 = (lane < 16) ? (2 * lane) : (2 * lane - 31);
    const bool lo16 = (lane < 16);

    // premasked conv coefficients: k_m = kap_m + sum_{d<m} wcr_d*murN + wci_d*muiP
    const int mo = lane & 15;
    float cwr[T - 1], cwi[T - 1];
    int cix[T - 1];
    #pragma unroll
    for (int d = 0; d < T - 1; ++d) {
        const bool act = d < mo;
        const int idx = act ? (mo - 1 - d) : 0;
        cwr[d] = act ? wcr[d] : 0.f;
        cwi[d] = act ? wci[d] : 0.f;
        cix[d] = 4 * idx;   // float index of murN_idx; muiP at +2
    }

    #pragma unroll 1
    for (int b = 0; b < NB; ++b) {
        const u64 XiN = f2mul(Xi, NEG1);

        // dots -> scalar-fold scatter: rows m (mur), 16+m (mui), 32+m (kap)
        #pragma unroll
        for (int m = 0; m < T; ++m) {
            const ulonglong2 ce = s_cel[wip][m][lane];
            const float2 a2 = up(f2fma(UEi[m], XiN, f2mul(UEr[m], Xr)));
            const float2 b2 = up(f2fma(UEi[m], Xr,  f2mul(UEr[m], Xi)));
            const float2 c2v = up(f2fma(ce.y, XiN, f2mul(ce.x, Xr)));
            sp[m * ROWP + lane]        = a2.x + a2.y;
            sp[(16 + m) * ROWP + lane] = b2.x + b2.y;
            sp[(32 + m) * ROWP + lane] = c2v.x + c2v.y;
        }
        __syncwarp();

        // rowsum: row1 (all lanes), row2 (lanes 16-31 duplicate 0-15)
        float rs, rs2;
        {
            ulonglong2 v0 = row1p[0], v1 = row1p[1], v2 = row1p[2], v3 = row1p[3];
            ulonglong2 v4 = row1p[4], v5 = row1p[5], v6 = row1p[6], v7 = row1p[7];
            u64 a0 = f2add(f2add(v0.x, v0.y), f2add(v4.x, v4.y));
            u64 a1 = f2add(f2add(v1.x, v1.y), f2add(v5.x, v5.y));
            u64 a2 = f2add(f2add(v2.x, v2.y), f2add(v6.x, v6.y));
            u64 a3 = f2add(f2add(v3.x, v3.y), f2add(v7.x, v7.y));
            const float2 f = up(f2add(f2add(a0, a1), f2add(a2, a3)));
            rs = f.x + f.y;
        }
        {
            ulonglong2 v0 = row2p[0], v1 = row2p[1], v2 = row2p[2], v3 = row2p[3];
            ulonglong2 v4 = row2p[4], v5 = row2p[5], v6 = row2p[6], v7 = row2p[7];
            u64 a0 = f2add(f2add(v0.x, v0.y), f2add(v4.x, v4.y));
            u64 a1 = f2add(f2add(v1.x, v1.y), f2add(v5.x, v5.y));
            u64 a2 = f2add(f2add(v2.x, v2.y), f2add(v6.x, v6.y));
            u64 a3 = f2add(f2add(v3.x, v3.y), f2add(v7.x, v7.y));
            const float2 f = up(f2add(f2add(a0, a1), f2add(a2, a3)));
            rs2 = f.x + f.y;
        }
        // merged branchless dup stores
        su_pair[idx1] = lo16 ? pk(-rs, -rs) : pk(rs, rs);
        su_aux[lane]  = lo16 ? pk(rs2, rs2) : pk(-rs, -rs);
        __syncwarp();

        // update: X' = E^T.*X + sum_i (murN_i,muiP_i,muiN_i) x (RrP,RiP)
        {
            u64 A0 = f2fma(ETi, XiN, f2mul(ETr, Xr));
            u64 B0 = f2fma(ETi, Xr,  f2mul(ETr, Xi));
            u64 A1 = ZERO, B1 = ZERO, A2 = ZERO, B2 = ZERO, A3 = ZERO, B3 = ZERO;
            #pragma unroll
            for (int i = 0; i < T; i += 4) {
                #pragma unroll
                for (int t = 0; t < 4; ++t) {
                    const int k = i + t;
                    const ulonglong2 pm = s_pair[wip][k];   // (murN, muiP)
                    const u64 mn = su_aux[16 + k];          // muiN
                    if (t == 0) {
                        A0 = f2fma(pm.x, RrP[k], f2fma(pm.y, RiP[k], A0));
                        B0 = f2fma(pm.x, RiP[k], f2fma(mn,  RrP[k], B0));
                    } else if (t == 1) {
                        A1 = f2fma(pm.x, RrP[k], f2fma(pm.y, RiP[k], A1));
                        B1 = f2fma(pm.x, RiP[k], f2fma(mn,  RrP[k], B1));
                    } else if (t == 2) {
                        A2 = f2fma(pm.x, RrP[k], f2fma(pm.y, RiP[k], A2));
                        B2 = f2fma(pm.x, RiP[k], f2fma(mn,  RrP[k], B2));
                    } else {
                        A3 = f2fma(pm.x, RrP[k], f2fma(pm.y, RiP[k], A3));
                        B3 = f2fma(pm.x, RiP[k], f2fma(mn,  RrP[k], B3));
                    }
                }
            }
            Xr = f2add(f2add(A0, A1), f2add(A2, A3));
            Xi = f2add(f2add(B0, B1), f2add(B2, B3));
        }

        // outputs: kv = kap[mo] + sum_d cwr[d]*murN[idx] + cwi[d]*muiP[idx]
        {
            float kv = af[2 * mo];
            #pragma unroll
            for (int d = 0; d < T - 1; ++d)
                kv = fmaf(cwr[d], pf[cix[d]], fmaf(cwi[d], pf[cix[d] + 2], kv));
            if (lo16) o_ptr[b * T + mo] = kv;
        }
    }

    // scalar tail (L % T != 0; unused for L=2048)
    for (int l = Lb; l < L; ++l) {
        float2 xr2 = up(Xr), xi2 = up(Xi);
        float xrr[2] = {xr2.x, xr2.y}, xii[2] = {xi2.x, xi2.y};
        float sr2 = 0.f, si2 = 0.f, kv = 0.f;
        #pragma unroll
        for (int s = 0; s < 2; ++s) {
            sr2 += C.ur[s] * xrr[s] - C.ui[s] * xii[s];
            si2 += C.ur[s] * xii[s] + C.ui[s] * xrr[s];
            kv  += C.c2r[s] * xrr[s] - C.c2i[s] * xii[s];
        }
        sr2 = wsum(sr2); si2 = wsum(si2); kv = wsum(kv);
        if (lane == 0) o_ptr[l] = kv;
        float nxr[2], nxi[2];
        #pragma unroll
        for (int s = 0; s < 2; ++s) {
            nxr[s] = C.er[s] * xrr[s] - C.ei[s] * xii[s]
                   - (sr2 * C.qr[s] - si2 * C.qi[s]);
            nxi[s] = C.er[s] * xii[s] + C.ei[s] * xrr[s]
                   - (sr2 * C.qi[s] + si2 * C.qr[s]);
        }
        Xr = pk(nxr[0], nxr[1]); Xi = pk(nxi[0], nxi[1]);
    }
}

extern "C" void kernel_launch(void* const* d_in, const int* in_sizes, int n_in,
                              void* d_out, int out_size) {
    const float* Ar = (const float*)d_in[0];
    const float* Ai = (const float*)d_in[1];
    const float* Br = (const float*)d_in[2];
    const float* Bi = (const float*)d_in[3];
    const float* Pr = (const float*)d_in[4];
    const float* Pi = (const float*)d_in[5];
    const float* Cr = (const float*)d_in[6];
    const float* Ci = (const float*)d_in[7];
    const float* ld = (const float*)d_in[8];
    float* out = (float*)d_out;

    const int H = in_sizes[8];          // 256
    const int L = out_size / H;         // 2048

    const int blocks = (H + 1) / 2;     // 2 heads per CTA, 1 warp each
    ssm_dplr_kernel<<<blocks, 64>>>(
        Ar, Ai, Br, Bi, Pr, Pi, Cr, Ci, ld, out, H, L);
}